// round 16
// baseline (speedup 1.0000x reference)
#include <cuda_runtime.h>

#define BSZ   8
#define NPTS  4096
#define CIN   128
#define COUT  256
#define MCTR  1024
#define SSAMP 64
#define NTILES 1024     // (NPTS/64)*(COUT/128)*BSZ

// Scratch (static device globals: no allocations allowed)
__device__ float g_pre[BSZ * NPTS * COUT];   // [b][n][o]  33.5 MB
__device__ int   g_fps[BSZ * MCTR];
__device__ int   g_idx[BSZ * MCTR * SSAMP];
__device__ int   g_smid[BSZ];                // SMs hosting FPS blocks
__device__ int   g_ready;                    // FPS blocks that published smid
__device__ int   g_tile;                     // GEMM tile work queue head

// Exact reference arithmetic: squares then left-to-right sum, no FMA contraction.
__device__ __forceinline__ float d2_rn(float ax, float ay, float az,
                                       float bx, float by, float bz) {
    float dx = ax - bx, dy = ay - by, dz = az - bz;
    return __fadd_rn(__fadd_rn(__fmul_rn(dx, dx), __fmul_rn(dy, dy)),
                     __fmul_rn(dz, dz));
}

// ---- packed f32x2 helpers (per-lane IEEE rn: bit-identical to scalar) ----
__device__ __forceinline__ unsigned long long pack2(float lo, float hi) {
    unsigned long long r;
    asm("mov.b64 %0, {%1, %2};" : "=l"(r) : "f"(lo), "f"(hi));
    return r;
}
__device__ __forceinline__ void unpack2(unsigned long long v, float& lo, float& hi) {
    asm("mov.b64 {%0, %1}, %2;" : "=f"(lo), "=f"(hi) : "l"(v));
}
__device__ __forceinline__ unsigned long long add2(unsigned long long a,
                                                   unsigned long long b) {
    unsigned long long r;
    asm("add.rn.f32x2 %0, %1, %2;" : "=l"(r) : "l"(a), "l"(b));
    return r;
}
__device__ __forceinline__ unsigned long long mul2(unsigned long long a,
                                                   unsigned long long b) {
    unsigned long long r;
    asm("mul.rn.f32x2 %0, %1, %2;" : "=l"(r) : "l"(a), "l"(b));
    return r;
}

__device__ __forceinline__ int ld_acq(const int* p) {
    int v;
    asm volatile("ld.acquire.gpu.global.s32 %0, [%1];" : "=r"(v) : "l"(p) : "memory");
    return v;
}
__device__ __forceinline__ int my_smid() {
    int s; asm("mov.u32 %0, %%smid;" : "=r"(s)); return s;
}

// ---------------------------------------------------------------------------
__global__ void reset_kernel() {
    if (threadIdx.x == 0) { g_ready = 0; g_tile = 0; }
}

// ---------------------------------------------------------------------------
// FPS v3: distance arithmetic bit-identical to the r10/r15 champion
// (packed f32x2, FMNMX mind update). Argmax restructured:
//  - in-loop tournament tree carries the index (ALU-pipe ops, hidden under
//    the fma-pipe bulk): contiguous-range merges + strict '>' keep the
//    LOWEST original index on all ties, exactly matching jnp.argmax.
//  - warp: REDUX(max val) + REDUX(min idx among attainers).
//  - block: leaders store (val,idx) into parity double-buffered slots; ONE
//    __syncthreads; every warp redundantly REDUXes the 8 winners (r6/r12-
//    validated) so Iv lands in registers — no atomicMin, no second barrier,
//    no s_widx reload on the critical path.
// ---------------------------------------------------------------------------
__device__ void fps_body(const float* __restrict__ xyz, int b) {
    const int tid = threadIdx.x;
    const int lane = tid & 31, warp = tid >> 5;

    __shared__ int s_val[2][8];
    __shared__ int s_idx[2][8];

    if (tid == 0) {
        g_smid[b] = my_smid();
        __threadfence();
        atomicAdd(&g_ready, 1);
    }

    const float* p = xyz + b * NPTS * 3;

    unsigned long long px2[8], py2[8], pz2[8];
    float mind[16];
#pragma unroll
    for (int j = 0; j < 8; j++) {
        int n0 = (2 * j) * 256 + tid;
        int n1 = (2 * j + 1) * 256 + tid;
        px2[j] = pack2(p[3 * n0 + 0], p[3 * n1 + 0]);
        py2[j] = pack2(p[3 * n0 + 1], p[3 * n1 + 1]);
        pz2[j] = pack2(p[3 * n0 + 2], p[3 * n1 + 2]);
        mind[2 * j] = 1e10f; mind[2 * j + 1] = 1e10f;
    }
    if (tid == 0) g_fps[b * MCTR] = 0;
    int Iv = 0;   // idx[0] = 0, in registers everywhere

    for (int t = 1; t < MCTR; t++) {
        const float lx = __ldg(p + 3 * Iv + 0);
        const float ly = __ldg(p + 3 * Iv + 1);
        const float lz = __ldg(p + 3 * Iv + 2);
        const unsigned long long nlx2 = pack2(-lx, -lx);
        const unsigned long long nly2 = pack2(-ly, -ly);
        const unsigned long long nlz2 = pack2(-lz, -lz);

#pragma unroll
        for (int j = 0; j < 8; j++) {
            unsigned long long dx2 = add2(px2[j], nlx2);
            unsigned long long dy2 = add2(py2[j], nly2);
            unsigned long long dz2 = add2(pz2[j], nlz2);
            unsigned long long s2 = add2(add2(mul2(dx2, dx2), mul2(dy2, dy2)),
                                         mul2(dz2, dz2));
            float s0, s1; unpack2(s2, s0, s1);
            mind[2 * j]     = fminf(mind[2 * j],     s0);
            mind[2 * j + 1] = fminf(mind[2 * j + 1], s1);
        }

        // tournament argmax over the 16 mind values (lowest k wins ties).
        // Contiguous-range merges: each node covers an ascending k-range and
        // strict '>' keeps the left (lower-k) side on ties.
        float v[8]; int ix[8];
#pragma unroll
        for (int k = 0; k < 8; k++) {
            ix[k] = (mind[2 * k + 1] > mind[2 * k]) ? (2 * k + 1) : (2 * k);
            v[k]  = fmaxf(mind[2 * k], mind[2 * k + 1]);
        }
#pragma unroll
        for (int k = 0; k < 4; k++) {
            ix[k] = (v[2 * k + 1] > v[2 * k]) ? ix[2 * k + 1] : ix[2 * k];
            v[k]  = fmaxf(v[2 * k], v[2 * k + 1]);
        }
#pragma unroll
        for (int k = 0; k < 2; k++) {
            ix[k] = (v[2 * k + 1] > v[2 * k]) ? ix[2 * k + 1] : ix[2 * k];
            v[k]  = fmaxf(v[2 * k], v[2 * k + 1]);
        }
        const int myk  = (v[1] > v[0]) ? ix[1] : ix[0];
        const float best = fmaxf(v[0], v[1]);

        // warp reduce: max value (>=0 so int bit order == value order),
        // then min point-index among value-attaining lanes.
        const int tb   = __float_as_int(best);
        const int wmax = __reduce_max_sync(0xffffffffu, tb);
        int cand = (tb == wmax) ? (myk * 256 + tid) : 0x7fffffff;
        const int widx = __reduce_min_sync(0xffffffffu, cand);

        if (lane == 0) {
            s_val[t & 1][warp] = wmax;
            s_idx[t & 1][warp] = widx;
        }
        __syncthreads();

        // every warp redundantly reduces the 8 warp winners
        int vb = (lane < 8) ? s_val[t & 1][lane] : (int)0x80000000;
        int vi = (lane < 8) ? s_idx[t & 1][lane] : 0x7fffffff;
        const int bmax = __reduce_max_sync(0xffffffffu, vb);
        int c2 = (vb == bmax) ? vi : 0x7fffffff;
        Iv = __reduce_min_sync(0xffffffffu, c2);

        if (tid == 0) g_fps[b * MCTR + t] = Iv;
    }
}

// ---------------------------------------------------------------------------
// One GEMM tile (r10 champion): pre[b][n][o] = sum_c feat[b][c][n] * W[o][c].
// ---------------------------------------------------------------------------
__device__ void gemm_tile(const float* __restrict__ feat,
                          const float* __restrict__ W, int gid,
                          float sF[32][65], float sW[32][129]) {
    const int b    = gid >> 7;
    const int rest = gid & 127;
    const int o0   = (rest & 1) * 128;
    const int n0   = (rest >> 1) * 64;

    const int tid = threadIdx.x;
    const int tx = tid & 15;
    const int ty = tid >> 4;

    float acc[4][8];
#pragma unroll
    for (int i = 0; i < 4; i++)
#pragma unroll
        for (int j = 0; j < 8; j++) acc[i][j] = 0.f;

    const float* fb = feat + b * CIN * NPTS;

    for (int k0 = 0; k0 < CIN; k0 += 32) {
#pragma unroll
        for (int i = 0; i < 8; i++) {
            int e = tid + i * 256;
            sF[e >> 6][e & 63] = fb[(k0 + (e >> 6)) * NPTS + n0 + (e & 63)];
        }
#pragma unroll
        for (int i = 0; i < 16; i++) {
            int e = tid + i * 256;
            sW[e & 31][e >> 5] = W[(o0 + (e >> 5)) * CIN + k0 + (e & 31)];
        }
        __syncthreads();
#pragma unroll
        for (int c = 0; c < 32; c++) {
            float fv[4], wv[8];
#pragma unroll
            for (int i = 0; i < 4; i++) fv[i] = sF[c][tx * 4 + i];
#pragma unroll
            for (int j = 0; j < 8; j++) wv[j] = sW[c][ty * 8 + j];
#pragma unroll
            for (int i = 0; i < 4; i++)
#pragma unroll
                for (int j = 0; j < 8; j++) acc[i][j] += fv[i] * wv[j];
        }
        __syncthreads();
    }

    float* pb = g_pre + b * NPTS * COUT;
#pragma unroll
    for (int i = 0; i < 4; i++) {
        int n = n0 + tx * 4 + i;
#pragma unroll
        for (int j = 0; j < 8; j++)
            pb[n * COUT + o0 + ty * 8 + j] = acc[i][j];
    }
}

// ---------------------------------------------------------------------------
// GEMM worker (r10 champion): exclude FPS SMs, then drain the tile queue.
// ---------------------------------------------------------------------------
__device__ void gemm_worker(const float* __restrict__ feat,
                            const float* __restrict__ W) {
    __shared__ float sF[32][65];
    __shared__ float sW[32][129];
    __shared__ int   s_ctl;

    const int tid = threadIdx.x;
    if (tid == 0) {
        while (ld_acq(&g_ready) < BSZ) __nanosleep(64);
        int sm = my_smid(), hit = 0;
#pragma unroll
        for (int i = 0; i < BSZ; i++) hit |= (g_smid[i] == sm);
        s_ctl = hit ? -1 : 0;
    }
    __syncthreads();
    if (s_ctl == -1) return;     // keep FPS SMs free of GEMM work

    for (;;) {
        if (tid == 0) s_ctl = atomicAdd(&g_tile, 1);
        __syncthreads();
        const int t = s_ctl;
        if (t >= NTILES) return;
        gemm_tile(feat, W, t, sF, sW);
        __syncthreads();
    }
}

// ---------------------------------------------------------------------------
__global__ __launch_bounds__(256) void fused_fps_gemm_kernel(
    const float* __restrict__ xyz, const float* __restrict__ feat,
    const float* __restrict__ W) {
    if (blockIdx.x < BSZ) fps_body(xyz, blockIdx.x);
    else                  gemm_worker(feat, W);
}

// ---------------------------------------------------------------------------
// Ball query (r10 verbatim): one warp per (b,m) center.
// ---------------------------------------------------------------------------
__global__ __launch_bounds__(256) void ballquery_kernel(const float* __restrict__ xyz) {
    const int tid = threadIdx.x, lane = tid & 31, w = tid >> 5;
    const int gw = blockIdx.x * 8 + w;
    const int b = gw >> 10, m = gw & (MCTR - 1);
    const float* p = xyz + b * NPTS * 3;

    const int ci = g_fps[b * MCTR + m];
    const float cx = p[3 * ci + 0], cy = p[3 * ci + 1], cz = p[3 * ci + 2];
    const float R2 = 0.1024f;

    int cnt = 0, firstIdx = 0;
    int* dst = g_idx + (b * MCTR + m) * SSAMP;

    for (int c0 = 0; c0 < NPTS && cnt < SSAMP; c0 += 32) {
        int n = c0 + lane;
        float d = d2_rn(p[3 * n + 0], p[3 * n + 1], p[3 * n + 2], cx, cy, cz);
        bool in = d < R2;
        unsigned msk = __ballot_sync(0xffffffffu, in);
        if (cnt == 0 && msk) firstIdx = c0 + (__ffs(msk) - 1);
        if (in) {
            int pos = cnt + __popc(msk & ((1u << lane) - 1u));
            if (pos < SSAMP) dst[pos] = n;
        }
        cnt += __popc(msk);
    }
    for (int pos = cnt + lane; pos < SSAMP; pos += 32) dst[pos] = firstIdx;
}

// ---------------------------------------------------------------------------
// Max-gather + folded BN/bias/ReLU (r13/r15 best-measured variant):
// 128 threads per block, two centers per block, gather unrolled 16.
// ---------------------------------------------------------------------------
__global__ __launch_bounds__(128) void maxpool_kernel(
    const float* __restrict__ bconv, const float* __restrict__ gamma,
    const float* __restrict__ beta,  const float* __restrict__ rmean,
    const float* __restrict__ rvar,  float* __restrict__ out) {
    const int b = blockIdx.y, tid = threadIdx.x;
    const int c = tid >> 6;              // center-in-block (0/1)
    const int ctid = tid & 63;           // thread-in-center
    const int m = blockIdx.x * 2 + c;

    __shared__ int soff[2][SSAMP];
    soff[c][ctid] = g_idx[(b * MCTR + m) * SSAMP + ctid] * COUT;
    __syncthreads();

    const float* pb = g_pre + b * NPTS * COUT + ctid * 4;
    float4 mx = make_float4(-3.4e38f, -3.4e38f, -3.4e38f, -3.4e38f);
#pragma unroll 16
    for (int s = 0; s < SSAMP; s++) {
        const float4 v = *(const float4*)(pb + soff[c][s]);
        mx.x = fmaxf(mx.x, v.x); mx.y = fmaxf(mx.y, v.y);
        mx.z = fmaxf(mx.z, v.z); mx.w = fmaxf(mx.w, v.w);
    }

    const float4 bc = ((const float4*)bconv)[ctid];
    const float4 gm = ((const float4*)gamma)[ctid];
    const float4 bt = ((const float4*)beta )[ctid];
    const float4 rm = ((const float4*)rmean)[ctid];
    const float4 rv = ((const float4*)rvar )[ctid];

    const int o = ctid * 4;
    out[(b * COUT + o + 0) * MCTR + m] =
        fmaxf((mx.x + bc.x - rm.x) * (gm.x * rsqrtf(rv.x + 1e-5f)) + bt.x, 0.f);
    out[(b * COUT + o + 1) * MCTR + m] =
        fmaxf((mx.y + bc.y - rm.y) * (gm.y * rsqrtf(rv.y + 1e-5f)) + bt.y, 0.f);
    out[(b * COUT + o + 2) * MCTR + m] =
        fmaxf((mx.z + bc.z - rm.z) * (gm.z * rsqrtf(rv.z + 1e-5f)) + bt.z, 0.f);
    out[(b * COUT + o + 3) * MCTR + m] =
        fmaxf((mx.w + bc.w - rm.w) * (gm.w * rsqrtf(rv.w + 1e-5f)) + bt.w, 0.f);
}

// ---------------------------------------------------------------------------
extern "C" void kernel_launch(void* const* d_in, const int* in_sizes, int n_in,
                              void* d_out, int out_size) {
    const float* xyz  = (const float*)d_in[0];
    const float* feat = (const float*)d_in[1];
    const float* W    = (const float*)d_in[2];
    const float* bcv  = (const float*)d_in[3];
    const float* gm   = (const float*)d_in[4];
    const float* bt   = (const float*)d_in[5];
    const float* rm   = (const float*)d_in[6];
    const float* rv   = (const float*)d_in[7];
    float* out = (float*)d_out;

    reset_kernel<<<1, 32>>>();
    fused_fps_gemm_kernel<<<BSZ + NTILES, 256>>>(xyz, feat, W);
    ballquery_kernel<<<(BSZ * MCTR) / 8, 256>>>(xyz);
    maxpool_kernel<<<dim3(MCTR / 2, BSZ), 128>>>(bcv, gm, bt, rm, rv, out);
}